// round 13
// baseline (speedup 1.0000x reference)
#include <cuda_runtime.h>
#include <cstdint>
#include <cstddef>

typedef unsigned long long ull;

// ---------------- constants ----------------
#define BB   256
#define SS   512
#define DD   200
#define HH   256
#define NJ   1024          // 4*H packed gate columns
#define NGRP 16            // batch groups (16 rows each)
#define NCOL 8             // column-group CTAs per batch group (32 hidden cols each)

// ---------------- device scratch ----------------
__device__ float    g_G[134217728];   // [B][S][1024] gate preactivations (x part + bias)
__device__ float    g_Wxp[DD * NJ];   // packed x-weights  [200][1024]
__device__ float    g_Whp[8 * 32768]; // packed h-weights  [colgrp][256][128]
__device__ float    g_biasp[NJ];
__device__ float    g_hbuf[2 * 65536];   // [parity][group][col 256][row 16]
__device__ ull      g_flags[32];         // [group][word]: 4x16-bit producer counters each

// ---------------- helpers ----------------
__device__ __forceinline__ ull pk2(float lo, float hi) {
    ull r; asm("mov.b64 %0,{%1,%2};" : "=l"(r) : "f"(lo), "f"(hi)); return r;
}
__device__ __forceinline__ void upk2(ull v, float& lo, float& hi) {
    asm("mov.b64 {%0,%1},%2;" : "=f"(lo), "=f"(hi) : "l"(v));
}
__device__ __forceinline__ ull ffma2(ull a, ull b, ull c) {
    ull d; asm("fma.rn.f32x2 %0,%1,%2,%3;" : "=l"(d) : "l"(a), "l"(b), "l"(c)); return d;
}
__device__ __forceinline__ float sigf(float x) {
    return __fdividef(1.0f, 1.0f + __expf(-x));
}
__device__ __forceinline__ float tanhfast(float x) {
    return __fdividef(2.0f, 1.0f + __expf(-2.0f * x)) - 1.0f;
}
__device__ __forceinline__ ull ldacq64(const ull* p) {
    ull v;
    asm volatile("ld.global.acquire.gpu.u64 %0,[%1];" : "=l"(v) : "l"(p) : "memory");
    return v;
}
__device__ __forceinline__ void red_release64(ull* p, ull v) {
    asm volatile("red.release.gpu.global.add.u64 [%0], %1;" :: "l"(p), "l"(v) : "memory");
}

// ---------------- kernel 0: pack weights ----------------
// j = g*128 + c*4 + gate  (g: col group 0..7, c: col-in-group 0..31, gate: i,f,o,z)
__global__ void k_pack(const float* __restrict__ Wi, const float* __restrict__ Wf,
                       const float* __restrict__ Wo, const float* __restrict__ Wz,
                       const float* __restrict__ bi, const float* __restrict__ bf,
                       const float* __restrict__ bo, const float* __restrict__ bz) {
    int idx = blockIdx.x * blockDim.x + threadIdx.x;
    if (idx < 456 * NJ) {
        int k = idx >> 10;
        int j = idx & (NJ - 1);
        int gate = j & 3;
        int c    = (j >> 2) & 31;
        int g    = j >> 7;
        int col  = g * 32 + c;
        const float* W = (gate == 0) ? Wi : (gate == 1) ? Wf : (gate == 2) ? Wo : Wz;
        float v = W[k * HH + col];
        if (k < DD) g_Wxp[k * NJ + j] = v;
        else        g_Whp[g * 32768 + (k - DD) * 128 + (j & 127)] = v;
    }
    if (idx < NJ) {
        int gate = idx & 3;
        int c    = (idx >> 2) & 31;
        int g    = idx >> 7;
        int col  = g * 32 + c;
        const float* bb = (gate == 0) ? bi : (gate == 1) ? bf : (gate == 2) ? bo : bz;
        g_biasp[idx] = bb[col];
    }
}

// ---------------- kernel 1: reset flags ----------------
__global__ void k_reset() {
    int i = threadIdx.x;
    if (i < 32) g_flags[i] = 0ull;
}

// ---------------- kernel 2: G = X @ Wxp + bias (EXACT R4/R10 version) ----------------
#define G1_BM 128
#define G1_BN 64
#define G1_BK 8
__global__ void __launch_bounds__(256) k_gemm1(const float* __restrict__ x) {
    __shared__ __align__(16) float As[2][G1_BK][G1_BM];
    __shared__ __align__(16) float Bs[2][G1_BK][G1_BN];

    int tid = threadIdx.x;
    int m0 = blockIdx.y * G1_BM;
    int n0 = blockIdx.x * G1_BN;

    int arow = tid >> 1;
    int akq  = (tid & 1) * 4;
    const float* aptr = x + (size_t)(m0 + arow) * DD + akq;

    int bkk = tid >> 5;
    int bn  = (tid & 31) * 2;
    const float* bptr = g_Wxp + (size_t)bkk * NJ + n0 + bn;

    int tx = tid & 15;   // 4 n-cols
    int ty = tid >> 4;   // 8 m-rows

    ull acc[4][4];
#pragma unroll
    for (int i = 0; i < 4; ++i)
#pragma unroll
        for (int j = 0; j < 4; ++j) acc[i][j] = 0ull;

    float4 av = *(const float4*)aptr;
    float2 bv = *(const float2*)bptr;
    As[0][akq + 0][arow] = av.x;
    As[0][akq + 1][arow] = av.y;
    As[0][akq + 2][arow] = av.z;
    As[0][akq + 3][arow] = av.w;
    *(float2*)&Bs[0][bkk][bn] = bv;

    for (int kc = 0; kc < 25; ++kc) {
        __syncthreads();
        int cur = kc & 1;
        if (kc < 24) {
            av = *(const float4*)(aptr + (kc + 1) * G1_BK);
            bv = *(const float2*)(bptr + (size_t)(kc + 1) * G1_BK * NJ);
        }
#pragma unroll
        for (int kk = 0; kk < G1_BK; ++kk) {
            const ull* ap2 = (const ull*)&As[cur][kk][ty * 8];
            ull A0 = ap2[0], A1 = ap2[1], A2 = ap2[2], A3 = ap2[3];
            float4 b4 = *(const float4*)&Bs[cur][kk][tx * 4];
            ull B0 = pk2(b4.x, b4.x), B1 = pk2(b4.y, b4.y);
            ull B2 = pk2(b4.z, b4.z), B3 = pk2(b4.w, b4.w);
            acc[0][0] = ffma2(A0, B0, acc[0][0]); acc[0][1] = ffma2(A0, B1, acc[0][1]);
            acc[0][2] = ffma2(A0, B2, acc[0][2]); acc[0][3] = ffma2(A0, B3, acc[0][3]);
            acc[1][0] = ffma2(A1, B0, acc[1][0]); acc[1][1] = ffma2(A1, B1, acc[1][1]);
            acc[1][2] = ffma2(A1, B2, acc[1][2]); acc[1][3] = ffma2(A1, B3, acc[1][3]);
            acc[2][0] = ffma2(A2, B0, acc[2][0]); acc[2][1] = ffma2(A2, B1, acc[2][1]);
            acc[2][2] = ffma2(A2, B2, acc[2][2]); acc[2][3] = ffma2(A2, B3, acc[2][3]);
            acc[3][0] = ffma2(A3, B0, acc[3][0]); acc[3][1] = ffma2(A3, B1, acc[3][1]);
            acc[3][2] = ffma2(A3, B2, acc[3][2]); acc[3][3] = ffma2(A3, B3, acc[3][3]);
        }
        if (kc < 24) {
            int nxt = cur ^ 1;
            As[nxt][akq + 0][arow] = av.x;
            As[nxt][akq + 1][arow] = av.y;
            As[nxt][akq + 2][arow] = av.z;
            As[nxt][akq + 3][arow] = av.w;
            *(float2*)&Bs[nxt][bkk][bn] = bv;
        }
    }

    float4 bias4 = *(const float4*)(g_biasp + n0 + tx * 4);
#pragma unroll
    for (int rp = 0; rp < 4; ++rp) {
        float4 r0, r1;
        upk2(acc[rp][0], r0.x, r1.x);
        upk2(acc[rp][1], r0.y, r1.y);
        upk2(acc[rp][2], r0.z, r1.z);
        upk2(acc[rp][3], r0.w, r1.w);
        r0.x += bias4.x; r0.y += bias4.y; r0.z += bias4.z; r0.w += bias4.w;
        r1.x += bias4.x; r1.y += bias4.y; r1.z += bias4.z; r1.w += bias4.w;
        size_t mrow = (size_t)m0 + ty * 8 + rp * 2;
        __stcs((float4*)(g_G + mrow * NJ + n0 + tx * 4), r0);
        __stcs((float4*)(g_G + (mrow + 1) * NJ + n0 + tx * 4), r1);
    }
}

// ---------------- kernel 3: persistent recurrence, 512 threads, k-split ----------------
// Thread t (half 0) and t+256 (half 1) each compute 4 producer-slices (128 k) of
// the same output; half-1 partials folded in via smem. 16 warps hide LDS latency.
// smem: Ws 131072 | stage 16384 | ms 32768 | partials 8192 = 188416 B
#define REC_SMEM_BYTES (131072 + 16384 + 32768 + 8192)
__global__ void __launch_bounds__(512, 1) k_rec(const float* __restrict__ mask,
                                                float* __restrict__ out) {
    extern __shared__ __align__(16) float sm[];
    float*  Ws  = sm;                        // [256 k][128 j]
    float4* stg = (float4*)(sm + 32768);     // [2 ph][4 sp][16 k2l][8 rp]
    float*  ms  = sm + 32768 + 4096;         // [512 s][16 r] mask transposed
    ull*    red = (ull*)(sm + 32768 + 4096 + 8192);  // [256 t][4 acc]

    int tid  = threadIdx.x;
    int grp  = blockIdx.x >> 3;
    int g    = blockIdx.x & 7;
    int half = tid >> 8;
    int lt   = tid & 255;
    int rp   = lt & 7;    // row pair: rows 2rp, 2rp+1
    int cq   = lt >> 3;   // hidden col in slice 0..31

    // preload weight slice (once for all 512 steps)
    {
        const float4* wsrc = (const float4*)(g_Whp + (size_t)g * 32768);
        float4* wdst = (float4*)Ws;
        for (int i = tid; i < 8192; i += 512) wdst[i] = wsrc[i];
    }
    // mask transpose: ms[s*16 + r]
    for (int i = tid; i < 8192; i += 512) {
        int r = i >> 9, s = i & 511;
        ms[s * 16 + r] = mask[(size_t)(grp * 16 + r) * SS + s];
    }
    __syncthreads();

    int b0 = grp * 16 + rp * 2;
    float c0 = 0.f, c1 = 0.f, sum0 = 0.f, sum1 = 0.f, msum0 = 0.f, msum1 = 0.f;
    const float* gbase = g_G + (size_t)b0 * SS * NJ + g * 128 + cq * 4;
    ull* flagw = &g_flags[grp * 2];
    ull  myinc = 1ull << (16 * (g & 3));
    int  myw   = g >> 2;
    const ull ONE2 = pk2(1.0f, 1.0f);

    // gather decode: entry e = tid (one entry per phase per thread)
    int e_sp  = tid >> 7;          // 0..3
    int e_k2l = (tid >> 3) & 15;
    int e_rp  = tid & 7;
    int jjA   = (g + e_sp) & 7;
    int jjB   = (g + 4 + e_sp) & 7;
    int slotA = (e_sp * 16 + e_k2l) * 8 + (e_rp ^ (e_k2l & 7));
    int slotB = 512 + slotA;

    for (int s = 0; s < SS; ++s) {
        ull a00, a01, a10, a11;
        float4 ga, gb;
        float2 mv;
        if (half == 0) {
            ga = __ldcs((const float4*)(gbase + (size_t)s * NJ));
            gb = __ldcs((const float4*)(gbase + (size_t)SS * NJ + (size_t)s * NJ));
            mv = *(const float2*)&ms[s * 16 + rp * 2];
            a00 = pk2(ga.x, ga.y); a01 = pk2(ga.z, ga.w);
            a10 = pk2(gb.x, gb.y); a11 = pk2(gb.z, gb.w);
        } else {
            a00 = a01 = a10 = a11 = 0ull;
        }

        if (s) {
            // one combined poll: all 8 producer fields >= s
            if (tid == 0) {
                unsigned us = (unsigned)s;
                for (;;) {
                    ull w0 = ldacq64(flagw);
                    ull w1 = ldacq64(flagw + 1);
                    if ((unsigned)(w0 & 0xFFFF) >= us &&
                        (unsigned)((w0 >> 16) & 0xFFFF) >= us &&
                        (unsigned)((w0 >> 32) & 0xFFFF) >= us &&
                        (unsigned)((w0 >> 48) & 0xFFFF) >= us &&
                        (unsigned)(w1 & 0xFFFF) >= us &&
                        (unsigned)((w1 >> 16) & 0xFFFF) >= us &&
                        (unsigned)((w1 >> 32) & 0xFFFF) >= us &&
                        (unsigned)((w1 >> 48) & 0xFFFF) >= us)
                        break;
                }
            }
            __syncthreads();

            // gather: every thread loads 1 entry of each phase (4x LDG.64)
            const float* hb = g_hbuf + ((size_t)(s & 1)) * 65536 + (size_t)grp * 4096;
            {
                const float* srcA = hb + ((jjA * 32 + e_k2l * 2) * 16 + e_rp * 2);
                const float* srcB = hb + ((jjB * 32 + e_k2l * 2) * 16 + e_rp * 2);
                float2 vaA = __ldcg((const float2*)srcA);
                float2 vbA = __ldcg((const float2*)(srcA + 16));
                float2 vaB = __ldcg((const float2*)srcB);
                float2 vbB = __ldcg((const float2*)(srcB + 16));
                stg[slotA] = make_float4(vaA.x, vaA.y, vbA.x, vbA.y);
                stg[slotB] = make_float4(vaB.x, vaB.y, vbB.x, vbB.y);
            }
            __syncthreads();

            // matvec: half 0 -> slices g..g+3 (stage A), half 1 -> g+4..g+7 (B)
            const ulonglong2* wq = (const ulonglong2*)Ws + cq;   // row k at +k*32
            const float4* hbase = stg + half * 512;
            int jbase = half * 4;
            for (int idx = 0; idx < 4; ++idx) {
                int jj = (g + jbase + idx) & 7;
                const ulonglong2* wj = wq + jj * 1024;
                const float4* hq = hbase + idx * 128;
#pragma unroll 8
                for (int i = 0; i < 16; ++i) {
                    ulonglong2 w0 = wj[i * 64];
                    ulonglong2 w1 = wj[i * 64 + 32];
                    float4 h4 = hq[i * 8 + (rp ^ (i & 7))];
                    ull ha0 = pk2(h4.x, h4.x), hb0 = pk2(h4.y, h4.y);
                    ull ha1 = pk2(h4.z, h4.z), hb1 = pk2(h4.w, h4.w);
                    a00 = ffma2(ha0, w0.x, a00); a01 = ffma2(ha0, w0.y, a01);
                    a10 = ffma2(hb0, w0.x, a10); a11 = ffma2(hb0, w0.y, a11);
                    a00 = ffma2(ha1, w1.x, a00); a01 = ffma2(ha1, w1.y, a01);
                    a10 = ffma2(hb1, w1.x, a10); a11 = ffma2(hb1, w1.y, a11);
                }
            }

            // half 1 exports partials; half 0 folds them in
            if (half) {
                ull* rd = red + lt * 4;
                rd[0] = a00; rd[1] = a01; rd[2] = a10; rd[3] = a11;
            }
            __syncthreads();
            if (half == 0) {
                const ull* rd = red + lt * 4;
                a00 = ffma2(rd[0], ONE2, a00);
                a01 = ffma2(rd[1], ONE2, a01);
                a10 = ffma2(rd[2], ONE2, a10);
                a11 = ffma2(rd[3], ONE2, a11);
            }
        }

        if (half == 0) {
            // nonlinearity + state update (gate order i,f,o,z)
            float ai0, af0, ao0, az0, ai1, af1, ao1, az1;
            upk2(a00, ai0, af0); upk2(a01, ao0, az0);
            upk2(a10, ai1, af1); upk2(a11, ao1, az1);
            float i0 = sigf(ai0), f0 = sigf(af0), o0 = sigf(ao0), z0 = tanhfast(az0);
            c0 = i0 * z0 + f0 * c0;
            float h0 = o0 * tanhfast(c0);
            float i1 = sigf(ai1), f1 = sigf(af1), o1 = sigf(ao1), z1 = tanhfast(az1);
            c1 = i1 * z1 + f1 * c1;
            float h1 = o1 * tanhfast(c1);
            sum0 += h0 * mv.x; msum0 += mv.x;
            sum1 += h1 * mv.y; msum1 += mv.y;

            // publish h[s+1]: [col][row] layout, one stcg.64
            float2 hv; hv.x = h0; hv.y = h1;
            __stcg((float2*)(g_hbuf + ((size_t)((s + 1) & 1)) * 65536 +
                             (size_t)grp * 4096 + (size_t)(g * 32 + cq) * 16 + rp * 2),
                   hv);
        }
        __syncthreads();
        if (tid == 0) red_release64(&flagw[myw], myinc);
    }

    if (half == 0) {
        int hcol = g * 32 + cq;
        out[(size_t)b0 * HH + hcol]       = sum0 * __fdividef(1.0f, msum0);
        out[(size_t)(b0 + 1) * HH + hcol] = sum1 * __fdividef(1.0f, msum1);
    }
}

// ---------------- launcher ----------------
extern "C" void kernel_launch(void* const* d_in, const int* in_sizes, int n_in,
                              void* d_out, int out_size) {
    const float* x    = (const float*)d_in[0];
    const float* mask = (const float*)d_in[1];
    const float* Wi   = (const float*)d_in[2];
    const float* bi   = (const float*)d_in[3];
    const float* Wf   = (const float*)d_in[4];
    const float* bf   = (const float*)d_in[5];
    const float* Wo   = (const float*)d_in[6];
    const float* bo   = (const float*)d_in[7];
    const float* Wz   = (const float*)d_in[8];
    const float* bz   = (const float*)d_in[9];
    float* out = (float*)d_out;

    cudaFuncSetAttribute(k_rec, cudaFuncAttributeMaxDynamicSharedMemorySize,
                         REC_SMEM_BYTES);

    k_pack<<<(456 * NJ + 255) / 256, 256>>>(Wi, Wf, Wo, Wz, bi, bf, bo, bz);
    k_reset<<<1, 32>>>();
    dim3 g1(NJ / G1_BN, (BB * SS) / G1_BM);
    k_gemm1<<<g1, 256>>>(x);
    k_rec<<<NGRP * NCOL, 512, REC_SMEM_BYTES>>>(mask, out);
}